// round 13
// baseline (speedup 1.0000x reference)
#include <cuda_runtime.h>
#include <cuda_fp16.h>
#include <mma.h>
#include <cstdint>

using namespace nvcuda;

#define NB 2
#define NS 2048
#define ND 1024
#define NH 16
#define NDH 64
#define XN (NB * NS * ND)      // 4194304
#define WN (ND * ND)           // 1048576 = 2^20

// half inputs for the projection GEMMs (Wq pre-scaled by 1/sqrt(DH)),
// and half projected Q/K/V in [b,h,s,dh] for the attention kernel.
__device__ __half g_xh[XN];
__device__ __half g_Wh[3 * WN];
__device__ __half g_Qh[NB * NH * NS * NDH];
__device__ __half g_Kh[NB * NH * NS * NDH];
__device__ __half g_Vh[NB * NH * NS * NDH];

__device__ __forceinline__ void cpa16(uint32_t dst, const void* src) {
    asm volatile("cp.async.cg.shared.global [%0], [%1], 16;\n" :: "r"(dst), "l"(src));
}
__device__ __forceinline__ uint32_t smem_u32(const void* p) {
    uint32_t a;
    asm("{ .reg .u64 t; cvta.to.shared.u64 t, %1; cvt.u32.u64 %0, t; }"
        : "=r"(a) : "l"(p));
    return a;
}

// ===========================================================================
// cvt: fp32 -> fp16 for x and the three weight matrices (Wq gets 0.125).
// ===========================================================================
__global__ __launch_bounds__(256) void cvt_kernel(const float* __restrict__ x,
                                                  const float* __restrict__ Wq,
                                                  const float* __restrict__ Wk,
                                                  const float* __restrict__ Wv)
{
    size_t e = ((size_t)blockIdx.x * 256 + threadIdx.x) * 4;
    const float* src;
    __half* dst;
    float sc = 1.0f;
    if (e < XN) {
        src = x + e;
        dst = g_xh + e;
    } else {
        size_t r = e - XN;
        int w = (int)(r >> 20);
        size_t off = r & (WN - 1);
        src = (w == 0 ? Wq : (w == 1 ? Wk : Wv)) + off;
        dst = g_Wh + (size_t)w * WN + off;
        if (w == 0) sc = 0.125f;   // 1/sqrt(64) folded into Wq
    }
    float4 v = *(const float4*)src;
    __half2* d2 = reinterpret_cast<__half2*>(dst);
    d2[0] = __floats2half2_rn(v.x * sc, v.y * sc);
    d2[1] = __floats2half2_rn(v.z * sc, v.w * sc);
}

// ===========================================================================
// Projection GEMM: fp16 wmma m16n16k16, 128x128 tile, K-tile 32,
// 3-stage cp.async pipeline. UNCHANGED from the measured 293.8us kernel.
// ===========================================================================
#define PKT 32
#define AS_S 40
#define BS_S 136
#define STAGE_H (128 * AS_S + PKT * BS_S)      // 9472 halves
#define PROJ_SMEM (3 * STAGE_H * 2)            // 56832 B

__global__ __launch_bounds__(256, 2) void proj_fp16()
{
    extern __shared__ char smraw[];
    __half* sh = reinterpret_cast<__half*>(smraw);

    const int which = blockIdx.z;
    const __half* __restrict__ W = g_Wh + (size_t)which * WN;
    __half* dst = (which == 0) ? g_Qh : (which == 1) ? g_Kh : g_Vh;

    const int m0 = blockIdx.y * 128;
    const int n0 = blockIdx.x * 128;
    const int tid = threadIdx.x;
    const int warp = tid >> 5;
    const int lane = tid & 31;
    const int wm = warp >> 2;
    const int wn = warp & 3;

    const __half* __restrict__ xbase = g_xh + (size_t)m0 * ND;

    wmma::fragment<wmma::accumulator, 16, 16, 16, float> acc[4][2];
    #pragma unroll
    for (int i = 0; i < 4; i++)
        #pragma unroll
        for (int j = 0; j < 2; j++)
            wmma::fill_fragment(acc[i][j], 0.0f);

    auto issue = [&](int ki, int st) {
        __half* As = sh + st * STAGE_H;
        __half* Bs = As + 128 * AS_S;
        const int kk0 = ki * PKT;
        #pragma unroll
        for (int i = 0; i < 2; i++) {
            int f = tid + i * 256;
            int row = f >> 2, c8 = (f & 3) * 8;
            cpa16(smem_u32(&As[row * AS_S + c8]),
                  xbase + (size_t)row * ND + kk0 + c8);
        }
        #pragma unroll
        for (int i = 0; i < 2; i++) {
            int f = tid + i * 256;
            int k = f >> 4, n8 = (f & 15) * 8;
            cpa16(smem_u32(&Bs[k * BS_S + n8]),
                  W + (size_t)(kk0 + k) * ND + n0 + n8);
        }
        asm volatile("cp.async.commit_group;\n" ::: "memory");
    };

    issue(0, 0);
    issue(1, 1);

    const int NIT = ND / PKT;
    for (int it = 0; it < NIT; it++) {
        if (it < NIT - 2) asm volatile("cp.async.wait_group 1;\n" ::: "memory");
        else              asm volatile("cp.async.wait_group 0;\n" ::: "memory");
        __syncthreads();
        if (it + 2 < NIT) issue(it + 2, (it + 2) % 3);

        const __half* As = sh + (it % 3) * STAGE_H;
        const __half* Bs = As + 128 * AS_S;

        #pragma unroll
        for (int ks = 0; ks < 2; ks++) {
            wmma::fragment<wmma::matrix_a, 16, 16, 16, __half, wmma::row_major> af[4];
            wmma::fragment<wmma::matrix_b, 16, 16, 16, __half, wmma::row_major> bf[2];
            #pragma unroll
            for (int i = 0; i < 4; i++)
                wmma::load_matrix_sync(af[i], &As[(wm * 64 + i * 16) * AS_S + ks * 16], AS_S);
            #pragma unroll
            for (int j = 0; j < 2; j++)
                wmma::load_matrix_sync(bf[j], &Bs[(ks * 16) * BS_S + wn * 32 + j * 16], BS_S);
            #pragma unroll
            for (int i = 0; i < 4; i++)
                #pragma unroll
                for (int j = 0; j < 2; j++)
                    wmma::mma_sync(acc[i][j], af[i], bf[j], acc[i][j]);
        }
    }

    __syncthreads();
    float* stg = reinterpret_cast<float*>(smraw) + warp * 256;

    #pragma unroll
    for (int i = 0; i < 4; i++) {
        #pragma unroll
        for (int j = 0; j < 2; j++) {
            wmma::store_matrix_sync(stg, acc[i][j], 16, wmma::mem_row_major);
            __syncwarp();
            const int row = lane >> 1;
            const int col = (lane & 1) * 8;
            float4 f0 = *(float4*)(stg + row * 16 + col);
            float4 f1 = *(float4*)(stg + row * 16 + col + 4);
            __half2 q0 = __floats2half2_rn(f0.x, f0.y);
            __half2 q1 = __floats2half2_rn(f0.z, f0.w);
            __half2 q2 = __floats2half2_rn(f1.x, f1.y);
            __half2 q3 = __floats2half2_rn(f1.z, f1.w);
            uint4 u;
            u.x = *reinterpret_cast<unsigned*>(&q0);
            u.y = *reinterpret_cast<unsigned*>(&q1);
            u.z = *reinterpret_cast<unsigned*>(&q2);
            u.w = *reinterpret_cast<unsigned*>(&q3);

            const int gm = m0 + wm * 64 + i * 16 + row;
            const int b = gm >> 11;
            const int s = gm & (NS - 1);
            const int gn = n0 + wn * 32 + j * 16;
            const int h = gn >> 6;
            const int cc = (gn & 63) + col;
            *(uint4*)(dst + ((size_t)(b * NH + h) * NS + s) * NDH + cc) = u;
            __syncwarp();
        }
    }
}

// ===========================================================================
// Flash attention v2 (causal): fp16 wmma + fp32 softmax.
// Q-tile 128 rows x K-tile 64, 256 threads = 8 warps (warp w: q-rows 16w..).
// Q fragments hoisted (loop-invariant); K/V double-buffered via cp.async.
// ===========================================================================
#define HS 72                          // half row stride (64 + 8)
#define FS 72                          // float row stride
#define KVSTG 18432                    // one K+V stage: 2 * 64*72*2
#define OFF_Q  0                       // Qh 128x72 half   18432 B
#define OFF_KV 18432                   // 2 stages         36864 B
#define OFF_P  55296                   // Ph 128x72 half   18432 B
#define OFF_S  73728                   // Sf 128x72 fp32   36864 B
#define OFF_O  110592                  // Of 128x72 fp32   36864 B
#define ATT_SMEM 147456

__global__ __launch_bounds__(256) void attn_fp16(float* __restrict__ out)
{
    extern __shared__ char smraw[];
    __half* Qh = reinterpret_cast<__half*>(smraw + OFF_Q);
    __half* Ph = reinterpret_cast<__half*>(smraw + OFF_P);
    float*  Sf = reinterpret_cast<float*>(smraw + OFF_S);
    float*  Of = reinterpret_cast<float*>(smraw + OFF_O);
    const uint32_t sbase = smem_u32(smraw);

    const int tid = threadIdx.x;
    const int warp = tid >> 5;
    const int bh = blockIdx.y;
    const int qt = gridDim.x - 1 - blockIdx.x;   // big q-tiles first
    const int q0 = qt * 128;

    const __half* __restrict__ Qg = g_Qh + (size_t)bh * NS * NDH;
    const __half* __restrict__ Kg = g_Kh + (size_t)bh * NS * NDH;
    const __half* __restrict__ Vg = g_Vh + (size_t)bh * NS * NDH;

    // Zero O accumulator (128x72 fp32); load Q tile (128x64 halves).
    #pragma unroll
    for (int t = 0; t < 36; t++)
        Of[tid + t * 256] = 0.0f;
    #pragma unroll
    for (int i = 0; i < 4; i++) {
        int idx = tid + i * 256;               // 1024 16B-chunks
        int r = idx >> 3, d8 = (idx & 7) * 8;
        *(uint4*)(Qh + r * HS + d8) = *(const uint4*)(Qg + (size_t)(q0 + r) * NDH + d8);
    }
    __syncthreads();

    // Hoisted Q fragments: warp's 16 q-rows x full d=64 (loop-invariant).
    wmma::fragment<wmma::matrix_a, 16, 16, 16, __half, wmma::row_major> af[4];
    #pragma unroll
    for (int kf = 0; kf < 4; kf++)
        wmma::load_matrix_sync(af[kf], Qh + (warp * 16) * HS + kf * 16, HS);

    // K/V tile loader into stage st (64 rows x 64 halves each, cp.async).
    auto issue = [&](int ktile, int st) {
        const uint32_t kb = sbase + OFF_KV + st * KVSTG;
        const size_t g0 = (size_t)ktile * 64 * NDH;
        #pragma unroll
        for (int j = 0; j < 2; j++) {
            int idx = tid + j * 256;
            int c = idx >> 3, d8 = (idx & 7) * 8;
            uint32_t so = (uint32_t)(c * HS + d8) * 2;
            cpa16(kb + so,        Kg + g0 + (size_t)c * NDH + d8);
            cpa16(kb + 9216 + so, Vg + g0 + (size_t)c * NDH + d8);
        }
        asm volatile("cp.async.commit_group;\n" ::: "memory");
    };

    const int nkt = 2 * qt + 2;    // k-tiles covering keys [0, q0+128)
    issue(0, 0);

    // Per-thread softmax state: row r = tid>>1, cols (tid&1)*32..+31 of 64.
    const int r = tid >> 1;
    const int cb = (tid & 1) * 32;
    float m = -1e30f, l = 0.0f;

    for (int i = 0; i < nkt; i++) {
        const int st = i & 1;
        const int k0 = i * 64;
        __half* Kh = reinterpret_cast<__half*>(smraw + OFF_KV + st * KVSTG);
        __half* Vh = Kh + 4608;    // 9216 B / 2

        __syncthreads();           // prev iter's PV reads of stage st^1 done
        if (i + 1 < nkt) issue(i + 1, st ^ 1);
        if (i + 1 < nkt) asm volatile("cp.async.wait_group 1;\n" ::: "memory");
        else             asm volatile("cp.async.wait_group 0;\n" ::: "memory");
        __syncthreads();           // stage st visible to all

        // S = Q K^T  (warp: 16 rows x 64 cols)
        #pragma unroll
        for (int nf = 0; nf < 4; nf++) {
            wmma::fragment<wmma::accumulator, 16, 16, 16, float> sacc;
            wmma::fill_fragment(sacc, 0.0f);
            #pragma unroll
            for (int kf = 0; kf < 4; kf++) {
                wmma::fragment<wmma::matrix_b, 16, 16, 16, __half, wmma::col_major> bf;
                wmma::load_matrix_sync(bf, Kh + (nf * 16) * HS + kf * 16, HS);
                wmma::mma_sync(sacc, af[kf], bf, sacc);
            }
            wmma::store_matrix_sync(Sf + (warp * 16) * FS + nf * 16, sacc, FS,
                                    wmma::mem_row_major);
        }
        __syncthreads();

        // Scalar fp32 online softmax; write P (half); rescale O.
        {
            float s[32];
            #pragma unroll
            for (int c = 0; c < 32; c += 4)
                *(float4*)&s[c] = *(float4*)&Sf[r * FS + cb + c];

            if (k0 + 63 > q0 + r) {           // diagonal/above tiles only
                #pragma unroll
                for (int c = 0; c < 32; c++)
                    if (k0 + cb + c > q0 + r) s[c] = -1e30f;
            }

            float mx = -1e30f;
            #pragma unroll
            for (int c = 0; c < 32; c++) mx = fmaxf(mx, s[c]);
            mx = fmaxf(mx, __shfl_xor_sync(0xffffffffu, mx, 1));

            float mnew = fmaxf(m, mx);
            float alpha = __expf(m - mnew);

            float ps = 0.0f;
            #pragma unroll
            for (int c = 0; c < 32; c++) {
                s[c] = __expf(s[c] - mnew);
                ps += s[c];
            }
            ps += __shfl_xor_sync(0xffffffffu, ps, 1);
            l = l * alpha + ps;
            m = mnew;

            __half2* pr = reinterpret_cast<__half2*>(Ph + r * HS + cb);
            #pragma unroll
            for (int c = 0; c < 16; c++)
                pr[c] = __floats2half2_rn(s[2 * c], s[2 * c + 1]);

            #pragma unroll
            for (int c = 0; c < 32; c += 4) {
                float4 o = *(float4*)&Of[r * FS + cb + c];
                o.x *= alpha; o.y *= alpha; o.z *= alpha; o.w *= alpha;
                *(float4*)&Of[r * FS + cb + c] = o;
            }
        }
        __syncthreads();

        // O += P V  (warp: 16 rows x 64 dh-cols, accum staged in smem fp32)
        {
            wmma::fragment<wmma::matrix_a, 16, 16, 16, __half, wmma::row_major> pf[4];
            #pragma unroll
            for (int kf = 0; kf < 4; kf++)
                wmma::load_matrix_sync(pf[kf], Ph + (warp * 16) * HS + kf * 16, HS);
            #pragma unroll
            for (int nf = 0; nf < 4; nf++) {
                wmma::fragment<wmma::accumulator, 16, 16, 16, float> oacc;
                wmma::load_matrix_sync(oacc, Of + (warp * 16) * FS + nf * 16, FS,
                                       wmma::mem_row_major);
                #pragma unroll
                for (int kf = 0; kf < 4; kf++) {
                    wmma::fragment<wmma::matrix_b, 16, 16, 16, __half, wmma::row_major> vf;
                    wmma::load_matrix_sync(vf, Vh + (kf * 16) * HS + nf * 16, HS);
                    wmma::mma_sync(oacc, pf[kf], vf, oacc);
                }
                wmma::store_matrix_sync(Of + (warp * 16) * FS + nf * 16, oacc, FS,
                                        wmma::mem_row_major);
            }
        }
    }
    __syncthreads();

    // Normalize and write out[b, q, h*64 + dh] (fp32).
    const int b = bh / NH;
    const int h = bh % NH;
    const float inv = 1.0f / l;
    float* op = out + ((size_t)(b * NS + q0 + r) * ND) + h * NDH + cb;
    #pragma unroll
    for (int c = 0; c < 32; c += 4) {
        float4 o = *(float4*)&Of[r * FS + cb + c];
        o.x *= inv; o.y *= inv; o.z *= inv; o.w *= inv;
        *(float4*)(op + c) = o;
    }
}

// ---------------------------------------------------------------------------
extern "C" void kernel_launch(void* const* d_in, const int* in_sizes, int n_in,
                              void* d_out, int out_size)
{
    const float* x  = (const float*)d_in[0];
    const float* Wq = (const float*)d_in[1];
    const float* Wk = (const float*)d_in[2];
    const float* Wv = (const float*)d_in[3];
    float* out = (float*)d_out;

    // 1. fp16 conversion (Wq scaled by 1/sqrt(DH))
    cvt_kernel<<<(XN + 3 * WN) / 4 / 256, 256>>>(x, Wq, Wk, Wv);

    // 2. Q/K/V projections (fp16 wmma, pipelined)
    cudaFuncSetAttribute(proj_fp16, cudaFuncAttributeMaxDynamicSharedMemorySize,
                         PROJ_SMEM);
    dim3 gproj(ND / 128, (NB * NS) / 128, 3);
    proj_fp16<<<gproj, 256, PROJ_SMEM>>>();

    // 3. causal flash attention (fp16 wmma + fp32 softmax, 128-q tiles)
    cudaFuncSetAttribute(attn_fp16, cudaFuncAttributeMaxDynamicSharedMemorySize,
                         ATT_SMEM);
    dim3 gattn(NS / 128, NB * NH);
    attn_fp16<<<gattn, 256, ATT_SMEM>>>(out);
}

// round 16
// speedup vs baseline: 1.0761x; 1.0761x over previous
#include <cuda_runtime.h>
#include <cuda_fp16.h>
#include <mma.h>
#include <cstdint>

using namespace nvcuda;

#define NB 2
#define NS 2048
#define ND 1024
#define NH 16
#define NDH 64
#define XN (NB * NS * ND)      // 4194304
#define WN (ND * ND)           // 1048576 = 2^20

// half inputs for the projection GEMMs (Wq pre-scaled by 1/sqrt(DH)),
// and half projected Q/K/V in [b,h,s,dh] for the attention kernel.
__device__ __half g_xh[XN];
__device__ __half g_Wh[3 * WN];
__device__ __half g_Qh[NB * NH * NS * NDH];
__device__ __half g_Kh[NB * NH * NS * NDH];
__device__ __half g_Vh[NB * NH * NS * NDH];

__device__ __forceinline__ void cpa16(uint32_t dst, const void* src) {
    asm volatile("cp.async.cg.shared.global [%0], [%1], 16;\n" :: "r"(dst), "l"(src));
}
__device__ __forceinline__ uint32_t smem_u32(const void* p) {
    uint32_t a;
    asm("{ .reg .u64 t; cvta.to.shared.u64 t, %1; cvt.u32.u64 %0, t; }"
        : "=r"(a) : "l"(p));
    return a;
}

// ===========================================================================
// cvt: fp32 -> fp16 for x and the three weight matrices (Wq gets 0.125).
// ===========================================================================
__global__ __launch_bounds__(256) void cvt_kernel(const float* __restrict__ x,
                                                  const float* __restrict__ Wq,
                                                  const float* __restrict__ Wk,
                                                  const float* __restrict__ Wv)
{
    size_t e = ((size_t)blockIdx.x * 256 + threadIdx.x) * 4;
    const float* src;
    __half* dst;
    float sc = 1.0f;
    if (e < XN) {
        src = x + e;
        dst = g_xh + e;
    } else {
        size_t r = e - XN;
        int w = (int)(r >> 20);
        size_t off = r & (WN - 1);
        src = (w == 0 ? Wq : (w == 1 ? Wk : Wv)) + off;
        dst = g_Wh + (size_t)w * WN + off;
        if (w == 0) sc = 0.125f;   // 1/sqrt(64) folded into Wq
    }
    float4 v = *(const float4*)src;
    __half2* d2 = reinterpret_cast<__half2*>(dst);
    d2[0] = __floats2half2_rn(v.x * sc, v.y * sc);
    d2[1] = __floats2half2_rn(v.z * sc, v.w * sc);
}

// ===========================================================================
// Projection GEMM: fp16 wmma m16n16k16, 128x128 tile, K-tile 32,
// 3-stage cp.async pipeline. UNCHANGED from the measured 293.8us kernel.
// ===========================================================================
#define PKT 32
#define AS_S 40
#define BS_S 136
#define STAGE_H (128 * AS_S + PKT * BS_S)      // 9472 halves
#define PROJ_SMEM (3 * STAGE_H * 2)            // 56832 B

__global__ __launch_bounds__(256, 2) void proj_fp16()
{
    extern __shared__ char smraw[];
    __half* sh = reinterpret_cast<__half*>(smraw);

    const int which = blockIdx.z;
    const __half* __restrict__ W = g_Wh + (size_t)which * WN;
    __half* dst = (which == 0) ? g_Qh : (which == 1) ? g_Kh : g_Vh;

    const int m0 = blockIdx.y * 128;
    const int n0 = blockIdx.x * 128;
    const int tid = threadIdx.x;
    const int warp = tid >> 5;
    const int lane = tid & 31;
    const int wm = warp >> 2;
    const int wn = warp & 3;

    const __half* __restrict__ xbase = g_xh + (size_t)m0 * ND;

    wmma::fragment<wmma::accumulator, 16, 16, 16, float> acc[4][2];
    #pragma unroll
    for (int i = 0; i < 4; i++)
        #pragma unroll
        for (int j = 0; j < 2; j++)
            wmma::fill_fragment(acc[i][j], 0.0f);

    auto issue = [&](int ki, int st) {
        __half* As = sh + st * STAGE_H;
        __half* Bs = As + 128 * AS_S;
        const int kk0 = ki * PKT;
        #pragma unroll
        for (int i = 0; i < 2; i++) {
            int f = tid + i * 256;
            int row = f >> 2, c8 = (f & 3) * 8;
            cpa16(smem_u32(&As[row * AS_S + c8]),
                  xbase + (size_t)row * ND + kk0 + c8);
        }
        #pragma unroll
        for (int i = 0; i < 2; i++) {
            int f = tid + i * 256;
            int k = f >> 4, n8 = (f & 15) * 8;
            cpa16(smem_u32(&Bs[k * BS_S + n8]),
                  W + (size_t)(kk0 + k) * ND + n0 + n8);
        }
        asm volatile("cp.async.commit_group;\n" ::: "memory");
    };

    issue(0, 0);
    issue(1, 1);

    const int NIT = ND / PKT;
    for (int it = 0; it < NIT; it++) {
        if (it < NIT - 2) asm volatile("cp.async.wait_group 1;\n" ::: "memory");
        else              asm volatile("cp.async.wait_group 0;\n" ::: "memory");
        __syncthreads();
        if (it + 2 < NIT) issue(it + 2, (it + 2) % 3);

        const __half* As = sh + (it % 3) * STAGE_H;
        const __half* Bs = As + 128 * AS_S;

        #pragma unroll
        for (int ks = 0; ks < 2; ks++) {
            wmma::fragment<wmma::matrix_a, 16, 16, 16, __half, wmma::row_major> af[4];
            wmma::fragment<wmma::matrix_b, 16, 16, 16, __half, wmma::row_major> bf[2];
            #pragma unroll
            for (int i = 0; i < 4; i++)
                wmma::load_matrix_sync(af[i], &As[(wm * 64 + i * 16) * AS_S + ks * 16], AS_S);
            #pragma unroll
            for (int j = 0; j < 2; j++)
                wmma::load_matrix_sync(bf[j], &Bs[(ks * 16) * BS_S + wn * 32 + j * 16], BS_S);
            #pragma unroll
            for (int i = 0; i < 4; i++)
                #pragma unroll
                for (int j = 0; j < 2; j++)
                    wmma::mma_sync(acc[i][j], af[i], bf[j], acc[i][j]);
        }
    }

    __syncthreads();
    float* stg = reinterpret_cast<float*>(smraw) + warp * 256;

    #pragma unroll
    for (int i = 0; i < 4; i++) {
        #pragma unroll
        for (int j = 0; j < 2; j++) {
            wmma::store_matrix_sync(stg, acc[i][j], 16, wmma::mem_row_major);
            __syncwarp();
            const int row = lane >> 1;
            const int col = (lane & 1) * 8;
            float4 f0 = *(float4*)(stg + row * 16 + col);
            float4 f1 = *(float4*)(stg + row * 16 + col + 4);
            __half2 q0 = __floats2half2_rn(f0.x, f0.y);
            __half2 q1 = __floats2half2_rn(f0.z, f0.w);
            __half2 q2 = __floats2half2_rn(f1.x, f1.y);
            __half2 q3 = __floats2half2_rn(f1.z, f1.w);
            uint4 u;
            u.x = *reinterpret_cast<unsigned*>(&q0);
            u.y = *reinterpret_cast<unsigned*>(&q1);
            u.z = *reinterpret_cast<unsigned*>(&q2);
            u.w = *reinterpret_cast<unsigned*>(&q3);

            const int gm = m0 + wm * 64 + i * 16 + row;
            const int b = gm >> 11;
            const int s = gm & (NS - 1);
            const int gn = n0 + wn * 32 + j * 16;
            const int h = gn >> 6;
            const int cc = (gn & 63) + col;
            *(uint4*)(dst + ((size_t)(b * NH + h) * NS + s) * NDH + cc) = u;
            __syncwarp();
        }
    }
}

// ===========================================================================
// Flash attention v3 (causal): fp16 wmma + fp32 softmax.
// 64-row Q tile, 128 threads = 4 warps (2 CTAs/SM co-residency preserved),
// + hoisted Q fragments + double-buffered K/V via cp.async.
// ===========================================================================
#define HS 72                          // half row stride (64 + 8)
#define FS 72                          // float row stride
#define KVSTG 18432                    // one K+V stage: 2 * 64*72*2 B
#define OFF_Q  0                       // Qh 64x72 half    9216 B
#define OFF_KV 9216                    // 2 K/V stages    36864 B
#define OFF_P  46080                   // Ph 64x72 half    9216 B
#define OFF_S  55296                   // Sf 64x72 fp32   18432 B
#define OFF_O  73728                   // Of 64x72 fp32   18432 B
#define ATT_SMEM 92160

__global__ __launch_bounds__(128) void attn_fp16(float* __restrict__ out)
{
    extern __shared__ char smraw[];
    __half* Qh = reinterpret_cast<__half*>(smraw + OFF_Q);
    __half* Ph = reinterpret_cast<__half*>(smraw + OFF_P);
    float*  Sf = reinterpret_cast<float*>(smraw + OFF_S);
    float*  Of = reinterpret_cast<float*>(smraw + OFF_O);
    const uint32_t sbase = smem_u32(smraw);

    const int tid = threadIdx.x;
    const int warp = tid >> 5;
    const int bh = blockIdx.y;
    const int qt = gridDim.x - 1 - blockIdx.x;   // big q-tiles first
    const int q0 = qt * 64;

    const __half* __restrict__ Qg = g_Qh + (size_t)bh * NS * NDH;
    const __half* __restrict__ Kg = g_Kh + (size_t)bh * NS * NDH;
    const __half* __restrict__ Vg = g_Vh + (size_t)bh * NS * NDH;

    // Zero O accumulator (64x72 fp32); load Q tile (64x64 halves).
    #pragma unroll
    for (int t = 0; t < 36; t++)
        Of[tid + t * 128] = 0.0f;
    #pragma unroll
    for (int i = 0; i < 4; i++) {
        int idx = tid + i * 128;               // 512 16B-chunks
        int r = idx >> 3, d8 = (idx & 7) * 8;
        *(uint4*)(Qh + r * HS + d8) = *(const uint4*)(Qg + (size_t)(q0 + r) * NDH + d8);
    }
    __syncthreads();

    // Hoisted Q fragments: warp's 16 q-rows x full d=64 (loop-invariant).
    wmma::fragment<wmma::matrix_a, 16, 16, 16, __half, wmma::row_major> af[4];
    #pragma unroll
    for (int kf = 0; kf < 4; kf++)
        wmma::load_matrix_sync(af[kf], Qh + (warp * 16) * HS + kf * 16, HS);

    // K/V tile loader into stage st (64 rows x 64 halves each, cp.async).
    auto issue = [&](int ktile, int st) {
        const uint32_t kb = sbase + OFF_KV + st * KVSTG;
        const size_t g0 = (size_t)ktile * 64 * NDH;
        #pragma unroll
        for (int j = 0; j < 4; j++) {
            int idx = tid + j * 128;
            int c = idx >> 3, d8 = (idx & 7) * 8;
            uint32_t so = (uint32_t)(c * HS + d8) * 2;
            cpa16(kb + so,        Kg + g0 + (size_t)c * NDH + d8);
            cpa16(kb + 9216 + so, Vg + g0 + (size_t)c * NDH + d8);
        }
        asm volatile("cp.async.commit_group;\n" ::: "memory");
    };

    const int nkt = qt + 1;    // k-tiles covering keys [0, q0+64)
    issue(0, 0);

    // Per-thread softmax state: row r = tid>>1, cols (tid&1)*32..+31 of 64.
    const int r = tid >> 1;
    const int cb = (tid & 1) * 32;
    float m = -1e30f, l = 0.0f;

    for (int i = 0; i < nkt; i++) {
        const int st = i & 1;
        const int k0 = i * 64;
        __half* Kh = reinterpret_cast<__half*>(smraw + OFF_KV + st * KVSTG);
        __half* Vh = Kh + 4608;    // 9216 B / 2

        __syncthreads();           // prev iter's PV reads of stage st^1 done
        if (i + 1 < nkt) issue(i + 1, st ^ 1);
        if (i + 1 < nkt) asm volatile("cp.async.wait_group 1;\n" ::: "memory");
        else             asm volatile("cp.async.wait_group 0;\n" ::: "memory");
        __syncthreads();           // stage st visible to all

        // S = Q K^T  (warp: 16 rows x 64 cols)
        #pragma unroll
        for (int nf = 0; nf < 4; nf++) {
            wmma::fragment<wmma::accumulator, 16, 16, 16, float> sacc;
            wmma::fill_fragment(sacc, 0.0f);
            #pragma unroll
            for (int kf = 0; kf < 4; kf++) {
                wmma::fragment<wmma::matrix_b, 16, 16, 16, __half, wmma::col_major> bf;
                wmma::load_matrix_sync(bf, Kh + (nf * 16) * HS + kf * 16, HS);
                wmma::mma_sync(sacc, af[kf], bf, sacc);
            }
            wmma::store_matrix_sync(Sf + (warp * 16) * FS + nf * 16, sacc, FS,
                                    wmma::mem_row_major);
        }
        __syncthreads();

        // Scalar fp32 online softmax; write P (half); rescale O.
        {
            float s[32];
            #pragma unroll
            for (int c = 0; c < 32; c += 4)
                *(float4*)&s[c] = *(float4*)&Sf[r * FS + cb + c];

            if (k0 + 63 > q0 + r) {           // diagonal tile only
                #pragma unroll
                for (int c = 0; c < 32; c++)
                    if (k0 + cb + c > q0 + r) s[c] = -1e30f;
            }

            float mx = -1e30f;
            #pragma unroll
            for (int c = 0; c < 32; c++) mx = fmaxf(mx, s[c]);
            mx = fmaxf(mx, __shfl_xor_sync(0xffffffffu, mx, 1));

            float mnew = fmaxf(m, mx);
            float alpha = __expf(m - mnew);

            float ps = 0.0f;
            #pragma unroll
            for (int c = 0; c < 32; c++) {
                s[c] = __expf(s[c] - mnew);
                ps += s[c];
            }
            ps += __shfl_xor_sync(0xffffffffu, ps, 1);
            l = l * alpha + ps;
            m = mnew;

            __half2* pr = reinterpret_cast<__half2*>(Ph + r * HS + cb);
            #pragma unroll
            for (int c = 0; c < 16; c++)
                pr[c] = __floats2half2_rn(s[2 * c], s[2 * c + 1]);

            #pragma unroll
            for (int c = 0; c < 32; c += 4) {
                float4 o = *(float4*)&Of[r * FS + cb + c];
                o.x *= alpha; o.y *= alpha; o.z *= alpha; o.w *= alpha;
                *(float4*)&Of[r * FS + cb + c] = o;
            }
        }
        __syncthreads();

        // O += P V  (warp: 16 rows x 64 dh-cols, accum staged in smem fp32)
        {
            wmma::fragment<wmma::matrix_a, 16, 16, 16, __half, wmma::row_major> pf[4];
            #pragma unroll
            for (int kf = 0; kf < 4; kf++)
                wmma::load_matrix_sync(pf[kf], Ph + (warp * 16) * HS + kf * 16, HS);
            #pragma unroll
            for (int nf = 0; nf < 4; nf++) {
                wmma::fragment<wmma::accumulator, 16, 16, 16, float> oacc;
                wmma::load_matrix_sync(oacc, Of + (warp * 16) * FS + nf * 16, FS,
                                       wmma::mem_row_major);
                #pragma unroll
                for (int kf = 0; kf < 4; kf++) {
                    wmma::fragment<wmma::matrix_b, 16, 16, 16, __half, wmma::row_major> vf;
                    wmma::load_matrix_sync(vf, Vh + (kf * 16) * HS + nf * 16, HS);
                    wmma::mma_sync(oacc, pf[kf], vf, oacc);
                }
                wmma::store_matrix_sync(Of + (warp * 16) * FS + nf * 16, oacc, FS,
                                        wmma::mem_row_major);
            }
        }
    }
    __syncthreads();

    // Normalize and write out[b, q, h*64 + dh] (fp32).
    const int b = bh / NH;
    const int h = bh % NH;
    const float inv = 1.0f / l;
    float* op = out + ((size_t)(b * NS + q0 + r) * ND) + h * NDH + cb;
    #pragma unroll
    for (int c = 0; c < 32; c += 4) {
        float4 o = *(float4*)&Of[r * FS + cb + c];
        o.x *= inv; o.y *= inv; o.z *= inv; o.w *= inv;
        *(float4*)(op + c) = o;
    }
}

// ---------------------------------------------------------------------------
extern "C" void kernel_launch(void* const* d_in, const int* in_sizes, int n_in,
                              void* d_out, int out_size)
{
    const float* x  = (const float*)d_in[0];
    const float* Wq = (const float*)d_in[1];
    const float* Wk = (const float*)d_in[2];
    const float* Wv = (const float*)d_in[3];
    float* out = (float*)d_out;

    // 1. fp16 conversion (Wq scaled by 1/sqrt(DH))
    cvt_kernel<<<(XN + 3 * WN) / 4 / 256, 256>>>(x, Wq, Wk, Wv);

    // 2. Q/K/V projections (fp16 wmma, pipelined)
    cudaFuncSetAttribute(proj_fp16, cudaFuncAttributeMaxDynamicSharedMemorySize,
                         PROJ_SMEM);
    dim3 gproj(ND / 128, (NB * NS) / 128, 3);
    proj_fp16<<<gproj, 256, PROJ_SMEM>>>();

    // 3. causal flash attention (fp16 wmma + fp32 softmax, 64-q tiles, 2 CTA/SM)
    cudaFuncSetAttribute(attn_fp16, cudaFuncAttributeMaxDynamicSharedMemorySize,
                         ATT_SMEM);
    dim3 gattn(NS / 64, NB * NH);
    attn_fp16<<<gattn, 128, ATT_SMEM>>>(out);
}